// round 15
// baseline (speedup 1.0000x reference)
#include <cuda_runtime.h>
#include <cuda_fp16.h>
#include <math.h>
#include <stdint.h>

// Problem constants
#define BB 4
#define SEQ 2048
#define DIM 2048
#define NH 16
#define HD 128
#define NTOK (BB * SEQ)        // 8192
#define QKVC (3 * DIM)         // 6144

// Scratch (device globals: allocation-free)
__device__ __half g_qkvh[(size_t)NTOK * QKVC];  // 96 MB fp16 qkv (post-RoPE)
__device__ __half g_ctxh[(size_t)NTOK * DIM];   // 32 MB fp16 ctx
__device__ __half g_xh[(size_t)NTOK * DIM];     // 32 MB fp16 x
__device__ __half g_w1h[(size_t)DIM * QKVC];    // 25 MB Wqkv fp16 [K][N]
__device__ __half g_w2h[(size_t)DIM * DIM];     // 8 MB  Wout fp16 [K][N]
__device__ float g_cos[SEQ * (HD / 2)];
__device__ float g_sin[SEQ * (HD / 2)];

// ---------------------------------------------------------------------------
// PTX helpers
// ---------------------------------------------------------------------------
__device__ __forceinline__ void cp_async16(const void* smem, const void* gmem) {
    uint32_t s = (uint32_t)__cvta_generic_to_shared(smem);
    asm volatile("cp.async.cg.shared.global [%0], [%1], 16;\n" :: "r"(s), "l"(gmem));
}
__device__ __forceinline__ void cp_commit() {
    asm volatile("cp.async.commit_group;\n");
}
__device__ __forceinline__ void cp_wait0() {
    asm volatile("cp.async.wait_group 0;\n");
}
__device__ __forceinline__ void cp_wait1() {
    asm volatile("cp.async.wait_group 1;\n");
}
__device__ __forceinline__ void mma_f16(float* c, const uint32_t* a, const uint32_t* b) {
    asm volatile(
        "mma.sync.aligned.m16n8k16.row.col.f32.f16.f16.f32 "
        "{%0,%1,%2,%3}, {%4,%5,%6,%7}, {%8,%9}, {%0,%1,%2,%3};\n"
        : "+f"(c[0]), "+f"(c[1]), "+f"(c[2]), "+f"(c[3])
        : "r"(a[0]), "r"(a[1]), "r"(a[2]), "r"(a[3]), "r"(b[0]), "r"(b[1]));
}
__device__ __forceinline__ void ldmatrix_x4(uint32_t& r0, uint32_t& r1,
                                            uint32_t& r2, uint32_t& r3,
                                            uint32_t addr) {
    asm volatile(
        "ldmatrix.sync.aligned.m8n8.x4.shared.b16 {%0,%1,%2,%3}, [%4];"
        : "=r"(r0), "=r"(r1), "=r"(r2), "=r"(r3) : "r"(addr));
}
__device__ __forceinline__ void ldmatrix_x4_trans(uint32_t& r0, uint32_t& r1,
                                                  uint32_t& r2, uint32_t& r3,
                                                  uint32_t addr) {
    asm volatile(
        "ldmatrix.sync.aligned.m8n8.x4.trans.shared.b16 {%0,%1,%2,%3}, [%4];"
        : "=r"(r0), "=r"(r1), "=r"(r2), "=r"(r3) : "r"(addr));
}
__device__ __forceinline__ uint32_t pack_half2(float a, float b) {
    __half2 h = __floats2half2_rn(a, b);
    return *(uint32_t*)&h;
}

// ---------------------------------------------------------------------------
// Prep: single fused fp32->fp16 conversion over x, Wqkv, Wout
// ---------------------------------------------------------------------------
#define N4_X  (NTOK * DIM / 4)            // 4,194,304
#define N4_W1 (DIM * QKVC / 4)            // 3,145,728
#define N4_W2 (DIM * DIM / 4)             // 1,048,576
#define N4_TOTAL (N4_X + N4_W1 + N4_W2)

__global__ void conv_all(const float* __restrict__ x,
                         const float* __restrict__ w1,
                         const float* __restrict__ w2) {
    int i = blockIdx.x * blockDim.x + threadIdx.x;
    if (i >= N4_TOTAL) return;
    const float* src;
    __half* dst;
    void* xh_p;
    if (i < N4_X) {
        src = x; dst = g_xh;
    } else if (i < N4_X + N4_W1) {
        i -= N4_X; src = w1; dst = g_w1h;
    } else {
        i -= N4_X + N4_W1; src = w2; dst = g_w2h;
    }
    float4 v = ((const float4*)src)[i];
    ((__half2*)dst)[2 * i] = __floats2half2_rn(v.x, v.y);
    ((__half2*)dst)[2 * i + 1] = __floats2half2_rn(v.z, v.w);
}

__global__ void build_rope_tables() {
    int idx = blockIdx.x * blockDim.x + threadIdx.x;
    if (idx >= SEQ * (HD / 2)) return;
    int pos = idx / (HD / 2);
    int i = idx % (HD / 2);
    float inv = (float)exp(-((double)(2 * i) / (double)HD) * log(10000.0));
    float ang = (float)pos * inv;
    float s, c;
    sincosf(ang, &s, &c);
    g_cos[idx] = c;
    g_sin[idx] = s;
}

// ---------------------------------------------------------------------------
// FP16 mma.sync GEMM (unchanged from R14).
// ---------------------------------------------------------------------------
#define BM 128
#define BN 128
#define HBK 64
#define HSTRIDE 72
#define BPAD 136
#define HA_STAGE (BM * HSTRIDE)
#define HB_STAGE (HBK * BPAD)
#define HSTAGE (HA_STAGE + HB_STAGE)
#define NSTAGE 3
#define GEMM_SMEM_BYTES (NSTAGE * HSTAGE * 2)   // 107520

__device__ __forceinline__ void load_a_tile(__half* S, const __half* G, int ldg,
                                            int k0, int tid) {
#pragma unroll
    for (int v = 0; v < 4; v++) {
        int idx = v * 256 + tid;
        int r = idx >> 3, ch = idx & 7;
        cp_async16(S + r * HSTRIDE + ch * 8, G + (size_t)r * ldg + k0 + ch * 8);
    }
}
__device__ __forceinline__ void load_b_tile(__half* S, const __half* G, int N,
                                            int bcol, int k0, int tid) {
#pragma unroll
    for (int v = 0; v < 4; v++) {
        int idx = v * 256 + tid;
        int r = idx >> 4, ch = idx & 15;
        cp_async16(S + r * BPAD + ch * 8,
                   G + (size_t)(k0 + r) * N + bcol + ch * 8);
    }
}

__global__ __launch_bounds__(256, 2)
void gemm_fp16(const __half* __restrict__ A, const __half* __restrict__ B,
               const float* __restrict__ bias, float* __restrict__ C,
               __half* __restrict__ Ch, int M, int N, int K, int do_rope) {
    extern __shared__ __half smh[];
    int tid = threadIdx.x;
    int brow = blockIdx.y * BM;
    int bcol = blockIdx.x * BN;
    int warp = tid >> 5, lane = tid & 31;
    int wm = warp >> 1, wn = warp & 1;
    int g = lane >> 2, t = lane & 3;

    float c[2][8][4];
#pragma unroll
    for (int i = 0; i < 2; i++)
#pragma unroll
        for (int j = 0; j < 8; j++)
#pragma unroll
            for (int r = 0; r < 4; r++) c[i][j][r] = 0.f;

    const int NK = K / HBK;
    const __half* Ab = A + (size_t)brow * K;

    uint32_t smh_u32 = (uint32_t)__cvta_generic_to_shared(smh);
    int lr = (lane & 7) + ((lane >> 3) & 1) * 8;
    int lk = (lane >> 4) * 8;
    uint32_t a_off = (uint32_t)((wm * 32 + lr) * HSTRIDE + lk) * 2;
    uint32_t b_off = (uint32_t)(HA_STAGE + (lane & 15) * BPAD + wn * 64 +
                                (lane >> 4) * 8) * 2;

#pragma unroll
    for (int s = 0; s < NSTAGE - 1; s++) {
        __half* st = smh + s * HSTAGE;
        load_a_tile(st, Ab, K, s * HBK, tid);
        load_b_tile(st + HA_STAGE, B, N, bcol, s * HBK, tid);
        cp_commit();
    }

    for (int kt = 0; kt < NK; kt++) {
        cp_wait1();
        __syncthreads();

        if (kt + NSTAGE - 1 < NK) {
            __half* st = smh + ((kt + NSTAGE - 1) % NSTAGE) * HSTAGE;
            load_a_tile(st, Ab, K, (kt + NSTAGE - 1) * HBK, tid);
            load_b_tile(st + HA_STAGE, B, N, bcol, (kt + NSTAGE - 1) * HBK, tid);
        }
        cp_commit();

        uint32_t stage_base = smh_u32 + (uint32_t)((kt % NSTAGE) * HSTAGE * 2);

#pragma unroll
        for (int j = 0; j < 4; j++) {
            uint32_t a[2][4], b[8][2];
            uint32_t ja = stage_base + a_off + (uint32_t)(j * 32);
#pragma unroll
            for (int mt = 0; mt < 2; mt++)
                ldmatrix_x4(a[mt][0], a[mt][1], a[mt][2], a[mt][3],
                            ja + (uint32_t)(mt * 16 * HSTRIDE * 2));
            uint32_t jb = stage_base + b_off + (uint32_t)(j * 16 * BPAD * 2);
#pragma unroll
            for (int p = 0; p < 4; p++) {
                uint32_t r0, r1, r2, r3;
                ldmatrix_x4_trans(r0, r1, r2, r3, jb + (uint32_t)(p * 32));
                b[2 * p][0] = r0; b[2 * p][1] = r1;
                b[2 * p + 1][0] = r2; b[2 * p + 1][1] = r3;
            }
#pragma unroll
            for (int mt = 0; mt < 2; mt++)
#pragma unroll
                for (int nt = 0; nt < 8; nt++)
                    mma_f16(c[mt][nt], a[mt], b[nt]);
        }
    }

    int rope_here = do_rope && (bcol < 2 * DIM);
#pragma unroll
    for (int mt = 0; mt < 2; mt++) {
        int r0 = brow + wm * 32 + mt * 16 + g;
        int pos0 = r0 & (SEQ - 1);
        int pos1 = (r0 + 8) & (SEQ - 1);
#pragma unroll
        for (int nt = 0; nt < 8; nt++) {
            int col = bcol + wn * 64 + nt * 8 + 2 * t;
            float b0 = bias[col], b1 = bias[col + 1];
            float v00 = c[mt][nt][0] + b0, v01 = c[mt][nt][1] + b1;
            float v10 = c[mt][nt][2] + b0, v11 = c[mt][nt][3] + b1;
            if (rope_here) {
                int i = (col & (HD - 1)) >> 1;
                float c0 = g_cos[pos0 * (HD / 2) + i];
                float s0 = g_sin[pos0 * (HD / 2) + i];
                float c1 = g_cos[pos1 * (HD / 2) + i];
                float s1 = g_sin[pos1 * (HD / 2) + i];
                float n00 = v00 * c0 - v01 * s0;
                float n01 = v01 * c0 + v00 * s0;
                float n10 = v10 * c1 - v11 * s1;
                float n11 = v11 * c1 + v10 * s1;
                v00 = n00; v01 = n01; v10 = n10; v11 = n11;
            }
            if (Ch) {
                *(__half2*)(Ch + (size_t)r0 * N + col) = __floats2half2_rn(v00, v01);
                *(__half2*)(Ch + (size_t)(r0 + 8) * N + col) = __floats2half2_rn(v10, v11);
            } else {
                *(float2*)(C + (size_t)r0 * N + col) = make_float2(v00, v01);
                *(float2*)(C + (size_t)(r0 + 8) * N + col) = make_float2(v10, v11);
            }
        }
    }
}

// ---------------------------------------------------------------------------
// FP16 flash attention — occ 3 target, FQT=64, Q in registers, 2-stage KV ring,
// register P, exp2 softmax; K fragments now via ldmatrix.x4.
// ---------------------------------------------------------------------------
#define FQT 64
#define FKT 64
#define KPADh 136
#define V_OFF (FKT * KPADh)
#define SKV (2 * FKT * KPADh)        // 17408 halves per KV stage
#define FA_NSTG 2
#define FA_SMEM_BYTES (FA_NSTG * SKV * 2)   // 69632

__device__ __forceinline__ void fa_load_kv_async(__half* dst, const __half* ksrc,
                                                 int tid) {
#pragma unroll
    for (int v = 0; v < 8; v++) {
        int idx = v * 128 + tid;
        int row = idx >> 4, ch = idx & 15;
        cp_async16(dst + row * KPADh + ch * 8, ksrc + (size_t)row * QKVC + ch * 8);
    }
    const __half* vsrc = ksrc + DIM;
#pragma unroll
    for (int v = 0; v < 8; v++) {
        int idx = v * 128 + tid;
        int row = idx >> 4, ch = idx & 15;
        cp_async16(dst + V_OFF + row * KPADh + ch * 8,
                   vsrc + (size_t)row * QKVC + ch * 8);
    }
}

__global__ __launch_bounds__(128, 3)
void flash_attn_f16(const __half* __restrict__ qkv, __half* __restrict__ ctx) {
    int qtile = (int)gridDim.x - 1 - (int)blockIdx.x;   // heavy tiles first
    int head = blockIdx.y, batch = blockIdx.z;
    int q0 = qtile * FQT;
    int tid = threadIdx.x, warp = tid >> 5, lane = tid & 31;
    int g = lane >> 2, t = lane & 3;

    extern __shared__ __half smh[];
    __half* KV0 = smh;

    const float scale2 = 0.08838834764831845f * 1.4426950408889634f;
    const __half* qbase = qkv + (size_t)(batch * SEQ + q0) * QKVC + head * HD;
    const __half* kvbase = qkv + (size_t)(batch * SEQ) * QKVC + DIM + head * HD;

    int ntiles = qtile + 1;

    // Prologue: KV[0]
    fa_load_kv_async(KV0, kvbase, tid);
    cp_commit();

    // Q -> registers, directly in A-fragment layout
    uint32_t qa[8][4];
    {
        const __half* q0p = qbase + (size_t)(warp * 16 + g) * QKVC + 2 * t;
        const __half* q1p = q0p + (size_t)8 * QKVC;
#pragma unroll
        for (int j = 0; j < 8; j++) {
            qa[j][0] = *(const uint32_t*)(q0p + 16 * j);
            qa[j][1] = *(const uint32_t*)(q1p + 16 * j);
            qa[j][2] = *(const uint32_t*)(q0p + 16 * j + 8);
            qa[j][3] = *(const uint32_t*)(q1p + 16 * j + 8);
        }
    }

    uint32_t kv0_u32 = (uint32_t)__cvta_generic_to_shared(KV0);
    // Shared lane-address pattern for both K (x4) and V (x4.trans) tiles:
    // row = lane&15, 16B column-half = lane>>4.
    uint32_t lm_lane = (((lane & 15) * KPADh) + ((lane >> 4) * 8)) * 2;

    float o[8][2][4];
#pragma unroll
    for (int mt = 0; mt < 8; mt++)
#pragma unroll
        for (int nt = 0; nt < 2; nt++)
#pragma unroll
            for (int r = 0; r < 4; r++) o[mt][nt][r] = 0.f;

    float m_a = -INFINITY, m_b = -INFINITY, l_a = 0.f, l_b = 0.f;
    int rowa = q0 + warp * 16 + g;
    int rowb = rowa + 8;

    int buf = 0;
    for (int kt = 0; kt < ntiles; kt++) {
        cp_wait0();        // KV[kt] resident
        __syncthreads();   // all warps done reading buf^1

        if (kt + 1 < ntiles) {
            fa_load_kv_async(KV0 + (buf ^ 1) * SKV,
                             kvbase + (size_t)(kt + 1) * FKT * QKVC, tid);
            cp_commit();
        }
        uint32_t k_lm = kv0_u32 + (buf * SKV) * 2 + lm_lane;
        uint32_t v_lm = k_lm + V_OFF * 2;

        // ---- S = Q @ K^T  (B-frags via ldmatrix.x4 non-trans) ----
        float sc[8][4];
#pragma unroll
        for (int nt = 0; nt < 8; nt++)
#pragma unroll
            for (int r = 0; r < 4; r++) sc[nt][r] = 0.f;

#pragma unroll
        for (int j = 0; j < 8; j++) {
            uint32_t b[8][2];
#pragma unroll
            for (int p = 0; p < 4; p++) {
                uint32_t r0, r1, r2, r3;
                ldmatrix_x4(r0, r1, r2, r3,
                            k_lm + (uint32_t)(p * 16 * KPADh) * 2 +
                            (uint32_t)(j * 32));
                b[2 * p][0] = r0; b[2 * p + 1][0] = r1;
                b[2 * p][1] = r2; b[2 * p + 1][1] = r3;
            }
#pragma unroll
            for (int nt = 0; nt < 8; nt++)
                mma_f16(sc[nt], qa[j], b[nt]);
        }

#pragma unroll
        for (int nt = 0; nt < 8; nt++)
#pragma unroll
            for (int r = 0; r < 4; r++) sc[nt][r] *= scale2;

        if (kt == qtile) {        // diagonal tile
            int k0g = kt * FKT;
#pragma unroll
            for (int nt = 0; nt < 8; nt++) {
                int col = k0g + nt * 8 + 2 * t;
                if (col > rowa) sc[nt][0] = -INFINITY;
                if (col + 1 > rowa) sc[nt][1] = -INFINITY;
                if (col > rowb) sc[nt][2] = -INFINITY;
                if (col + 1 > rowb) sc[nt][3] = -INFINITY;
            }
        }

        // ---- online softmax (exp2 domain, tree reductions) ----
        float ma0 = -INFINITY, ma1 = -INFINITY, mb0 = -INFINITY, mb1 = -INFINITY;
#pragma unroll
        for (int nt = 0; nt < 8; nt += 2) {
            ma0 = fmaxf(ma0, fmaxf(sc[nt][0], sc[nt][1]));
            ma1 = fmaxf(ma1, fmaxf(sc[nt + 1][0], sc[nt + 1][1]));
            mb0 = fmaxf(mb0, fmaxf(sc[nt][2], sc[nt][3]));
            mb1 = fmaxf(mb1, fmaxf(sc[nt + 1][2], sc[nt + 1][3]));
        }
        float tma = fmaxf(ma0, ma1), tmb = fmaxf(mb0, mb1);
        tma = fmaxf(tma, __shfl_xor_sync(0xffffffff, tma, 1));
        tma = fmaxf(tma, __shfl_xor_sync(0xffffffff, tma, 2));
        tmb = fmaxf(tmb, __shfl_xor_sync(0xffffffff, tmb, 1));
        tmb = fmaxf(tmb, __shfl_xor_sync(0xffffffff, tmb, 2));

        float nma = fmaxf(m_a, tma), nmb = fmaxf(m_b, tmb);
        float ca = exp2f(m_a - nma), cb = exp2f(m_b - nmb);
        m_a = nma; m_b = nmb;

        uint32_t pb[8][2];
        float sA0 = 0.f, sA1 = 0.f, sB0 = 0.f, sB1 = 0.f;
#pragma unroll
        for (int nt = 0; nt < 8; nt += 2) {
            float p0 = exp2f(sc[nt][0] - nma);
            float p1 = exp2f(sc[nt][1] - nma);
            float p2 = exp2f(sc[nt][2] - nmb);
            float p3 = exp2f(sc[nt][3] - nmb);
            pb[nt][0] = pack_half2(p0, p1);
            pb[nt][1] = pack_half2(p2, p3);
            sA0 += p0 + p1;
            sB0 += p2 + p3;
            float q0f = exp2f(sc[nt + 1][0] - nma);
            float q1f = exp2f(sc[nt + 1][1] - nma);
            float q2f = exp2f(sc[nt + 1][2] - nmb);
            float q3f = exp2f(sc[nt + 1][3] - nmb);
            pb[nt + 1][0] = pack_half2(q0f, q1f);
            pb[nt + 1][1] = pack_half2(q2f, q3f);
            sA1 += q0f + q1f;
            sB1 += q2f + q3f;
        }
        float sa = sA0 + sA1, sb = sB0 + sB1;
        sa += __shfl_xor_sync(0xffffffff, sa, 1);
        sa += __shfl_xor_sync(0xffffffff, sa, 2);
        sb += __shfl_xor_sync(0xffffffff, sb, 1);
        sb += __shfl_xor_sync(0xffffffff, sb, 2);
        l_a = l_a * ca + sa;
        l_b = l_b * cb + sb;

        // ---- rescale O^T ----
        float c0a = __shfl_sync(0xffffffff, ca, 8 * t);
        float c1a = __shfl_sync(0xffffffff, ca, 8 * t + 4);
        float c0b = __shfl_sync(0xffffffff, cb, 8 * t);
        float c1b = __shfl_sync(0xffffffff, cb, 8 * t + 4);
#pragma unroll
        for (int mt = 0; mt < 8; mt++) {
            o[mt][0][0] *= c0a; o[mt][0][1] *= c1a;
            o[mt][0][2] *= c0a; o[mt][0][3] *= c1a;
            o[mt][1][0] *= c0b; o[mt][1][1] *= c1b;
            o[mt][1][2] *= c0b; o[mt][1][3] *= c1b;
        }

        // ---- O^T += V^T @ P^T ----
#pragma unroll
        for (int j = 0; j < 4; j++) {
            uint32_t b0[2] = {pb[2 * j][0], pb[2 * j + 1][0]};
            uint32_t b1[2] = {pb[2 * j][1], pb[2 * j + 1][1]};
#pragma unroll
            for (int mt = 0; mt < 8; mt++) {
                uint32_t r0, r1, r2, r3;
                ldmatrix_x4_trans(r0, r1, r2, r3,
                                  v_lm + (uint32_t)(16 * j * KPADh + mt * 16) * 2);
                uint32_t a[4] = {r0, r2, r1, r3};
                mma_f16(o[mt][0], a, b0);
                mma_f16(o[mt][1], a, b1);
            }
        }

        buf ^= 1;
    }

    // ---- epilogue: O = O^T / l (l via shfl), fp16 out ----
    float l0a = __shfl_sync(0xffffffff, l_a, 8 * t);
    float l1a = __shfl_sync(0xffffffff, l_a, 8 * t + 4);
    float l0b = __shfl_sync(0xffffffff, l_b, 8 * t);
    float l1b = __shfl_sync(0xffffffff, l_b, 8 * t + 4);

#pragma unroll
    for (int nt = 0; nt < 2; nt++) {
        float il0 = 1.0f / (nt ? l0b : l0a);
        float il1 = 1.0f / (nt ? l1b : l1a);
        int q_loc = warp * 16 + nt * 8 + 2 * t;
        size_t r0 = (size_t)(batch * SEQ + q0 + q_loc) * DIM + head * HD;
        size_t r1 = r0 + DIM;
#pragma unroll
        for (int mt = 0; mt < 8; mt++) {
            int d = mt * 16 + g;
            ctx[r0 + d] = __float2half_rn(o[mt][nt][0] * il0);
            ctx[r1 + d] = __float2half_rn(o[mt][nt][1] * il1);
            ctx[r0 + d + 8] = __float2half_rn(o[mt][nt][2] * il0);
            ctx[r1 + d + 8] = __float2half_rn(o[mt][nt][3] * il1);
        }
    }
}

// ---------------------------------------------------------------------------
// Launch
// ---------------------------------------------------------------------------
extern "C" void kernel_launch(void* const* d_in, const int* in_sizes, int n_in,
                              void* d_out, int out_size) {
    const float* x      = (const float*)d_in[0];
    const float* Wqkv_w = (const float*)d_in[2];
    const float* Wqkv_b = (const float*)d_in[3];
    const float* Wout_w = (const float*)d_in[4];
    const float* Wout_b = (const float*)d_in[5];
    float* out = (float*)d_out;

    void *qkv_p, *ctx_p, *xh_p, *w1_p, *w2_p;
    cudaGetSymbolAddress(&qkv_p, g_qkvh);
    cudaGetSymbolAddress(&ctx_p, g_ctxh);
    cudaGetSymbolAddress(&xh_p, g_xh);
    cudaGetSymbolAddress(&w1_p, g_w1h);
    cudaGetSymbolAddress(&w2_p, g_w2h);
    __half* qkv = (__half*)qkv_p;
    __half* ctx = (__half*)ctx_p;
    __half* xh  = (__half*)xh_p;
    __half* w1h = (__half*)w1_p;
    __half* w2h = (__half*)w2_p;

    cudaFuncSetAttribute(gemm_fp16, cudaFuncAttributeMaxDynamicSharedMemorySize,
                         GEMM_SMEM_BYTES);
    cudaFuncSetAttribute(flash_attn_f16,
                         cudaFuncAttributeMaxDynamicSharedMemorySize, FA_SMEM_BYTES);

    // 0) Prep: single fused fp32 -> fp16 conversion
    conv_all<<<(N4_TOTAL + 255) / 256, 256>>>(x, Wqkv_w, Wout_w);

    // 1) RoPE tables (fp32 sincos)
    build_rope_tables<<<(SEQ * (HD / 2) + 255) / 256, 256>>>();

    // 2) QKV projection (fp16 MMA) with fused RoPE, fp16 output
    gemm_fp16<<<dim3(QKVC / BN, NTOK / BM), 256, GEMM_SMEM_BYTES>>>(
        xh, w1h, Wqkv_b, nullptr, qkv, NTOK, QKVC, DIM, 1);

    // 3) Flash attention (fp16 MMA; fp16 ctx)
    flash_attn_f16<<<dim3(SEQ / FQT, NH, BB), 128, FA_SMEM_BYTES>>>(qkv, ctx);

    // 4) Output projection (fp16 MMA, fp32 output)
    gemm_fp16<<<dim3(DIM / BN, NTOK / BM), 256, GEMM_SMEM_BYTES>>>(
        ctx, w2h, Wout_b, out, nullptr, NTOK, DIM, DIM, 0);
}

// round 16
// speedup vs baseline: 1.0131x; 1.0131x over previous
#include <cuda_runtime.h>
#include <cuda_fp16.h>
#include <math.h>
#include <stdint.h>

// Problem constants
#define BB 4
#define SEQ 2048
#define DIM 2048
#define NH 16
#define HD 128
#define NTOK (BB * SEQ)        // 8192
#define QKVC (3 * DIM)         // 6144

// Scratch (device globals: allocation-free)
__device__ __half g_qkvh[(size_t)NTOK * QKVC];  // 96 MB fp16 qkv (post-RoPE)
__device__ __half g_ctxh[(size_t)NTOK * DIM];   // 32 MB fp16 ctx
__device__ __half g_xh[(size_t)NTOK * DIM];     // 32 MB fp16 x
__device__ __half g_w1h[(size_t)DIM * QKVC];    // 25 MB Wqkv fp16 [K][N]
__device__ __half g_w2h[(size_t)DIM * DIM];     // 8 MB  Wout fp16 [K][N]
__device__ float g_cos[SEQ * (HD / 2)];
__device__ float g_sin[SEQ * (HD / 2)];

// ---------------------------------------------------------------------------
// PTX helpers
// ---------------------------------------------------------------------------
__device__ __forceinline__ void cp_async16(const void* smem, const void* gmem) {
    uint32_t s = (uint32_t)__cvta_generic_to_shared(smem);
    asm volatile("cp.async.cg.shared.global [%0], [%1], 16;\n" :: "r"(s), "l"(gmem));
}
__device__ __forceinline__ void cp_commit() {
    asm volatile("cp.async.commit_group;\n");
}
__device__ __forceinline__ void cp_wait0() {
    asm volatile("cp.async.wait_group 0;\n");
}
__device__ __forceinline__ void cp_wait1() {
    asm volatile("cp.async.wait_group 1;\n");
}
__device__ __forceinline__ void mma_f16(float* c, const uint32_t* a, const uint32_t* b) {
    asm volatile(
        "mma.sync.aligned.m16n8k16.row.col.f32.f16.f16.f32 "
        "{%0,%1,%2,%3}, {%4,%5,%6,%7}, {%8,%9}, {%0,%1,%2,%3};\n"
        : "+f"(c[0]), "+f"(c[1]), "+f"(c[2]), "+f"(c[3])
        : "r"(a[0]), "r"(a[1]), "r"(a[2]), "r"(a[3]), "r"(b[0]), "r"(b[1]));
}
__device__ __forceinline__ void ldmatrix_x4(uint32_t& r0, uint32_t& r1,
                                            uint32_t& r2, uint32_t& r3,
                                            uint32_t addr) {
    asm volatile(
        "ldmatrix.sync.aligned.m8n8.x4.shared.b16 {%0,%1,%2,%3}, [%4];"
        : "=r"(r0), "=r"(r1), "=r"(r2), "=r"(r3) : "r"(addr));
}
__device__ __forceinline__ void ldmatrix_x4_trans(uint32_t& r0, uint32_t& r1,
                                                  uint32_t& r2, uint32_t& r3,
                                                  uint32_t addr) {
    asm volatile(
        "ldmatrix.sync.aligned.m8n8.x4.trans.shared.b16 {%0,%1,%2,%3}, [%4];"
        : "=r"(r0), "=r"(r1), "=r"(r2), "=r"(r3) : "r"(addr));
}
__device__ __forceinline__ uint32_t pack_half2(float a, float b) {
    __half2 h = __floats2half2_rn(a, b);
    return *(uint32_t*)&h;
}

// ---------------------------------------------------------------------------
// Prep: fused fp32->fp16 conversion (x, Wqkv, Wout) + RoPE tables
// ---------------------------------------------------------------------------
#define N4_X  (NTOK * DIM / 4)
#define N4_W1 (DIM * QKVC / 4)
#define N4_W2 (DIM * DIM / 4)
#define N4_TOTAL (N4_X + N4_W1 + N4_W2)
#define NTAB (SEQ * (HD / 2))
#define PREP_TOTAL (N4_TOTAL + NTAB)

__global__ void prep_all(const float* __restrict__ x,
                         const float* __restrict__ w1,
                         const float* __restrict__ w2) {
    int i = blockIdx.x * blockDim.x + threadIdx.x;
    if (i >= PREP_TOTAL) return;
    if (i >= N4_TOTAL) {
        int idx = i - N4_TOTAL;
        int pos = idx / (HD / 2);
        int k = idx % (HD / 2);
        float inv = (float)exp(-((double)(2 * k) / (double)HD) * log(10000.0));
        float ang = (float)pos * inv;
        float s, c;
        sincosf(ang, &s, &c);
        g_cos[idx] = c;
        g_sin[idx] = s;
        return;
    }
    const float* src;
    __half* dst;
    if (i < N4_X) {
        src = x; dst = g_xh;
    } else if (i < N4_X + N4_W1) {
        i -= N4_X; src = w1; dst = g_w1h;
    } else {
        i -= N4_X + N4_W1; src = w2; dst = g_w2h;
    }
    float4 v = ((const float4*)src)[i];
    ((__half2*)dst)[2 * i] = __floats2half2_rn(v.x, v.y);
    ((__half2*)dst)[2 * i + 1] = __floats2half2_rn(v.z, v.w);
}

// ---------------------------------------------------------------------------
// FP16 mma.sync GEMM (unchanged from R15).
// ---------------------------------------------------------------------------
#define BM 128
#define BN 128
#define HBK 64
#define HSTRIDE 72
#define BPAD 136
#define HA_STAGE (BM * HSTRIDE)
#define HB_STAGE (HBK * BPAD)
#define HSTAGE (HA_STAGE + HB_STAGE)
#define NSTAGE 3
#define GEMM_SMEM_BYTES (NSTAGE * HSTAGE * 2)   // 107520

__device__ __forceinline__ void load_a_tile(__half* S, const __half* G, int ldg,
                                            int k0, int tid) {
#pragma unroll
    for (int v = 0; v < 4; v++) {
        int idx = v * 256 + tid;
        int r = idx >> 3, ch = idx & 7;
        cp_async16(S + r * HSTRIDE + ch * 8, G + (size_t)r * ldg + k0 + ch * 8);
    }
}
__device__ __forceinline__ void load_b_tile(__half* S, const __half* G, int N,
                                            int bcol, int k0, int tid) {
#pragma unroll
    for (int v = 0; v < 4; v++) {
        int idx = v * 256 + tid;
        int r = idx >> 4, ch = idx & 15;
        cp_async16(S + r * BPAD + ch * 8,
                   G + (size_t)(k0 + r) * N + bcol + ch * 8);
    }
}

__global__ __launch_bounds__(256, 2)
void gemm_fp16(const __half* __restrict__ A, const __half* __restrict__ B,
               const float* __restrict__ bias, float* __restrict__ C,
               __half* __restrict__ Ch, int M, int N, int K, int do_rope) {
    extern __shared__ __half smh[];
    int tid = threadIdx.x;
    int brow = blockIdx.y * BM;
    int bcol = blockIdx.x * BN;
    int warp = tid >> 5, lane = tid & 31;
    int wm = warp >> 1, wn = warp & 1;
    int g = lane >> 2, t = lane & 3;

    float c[2][8][4];
#pragma unroll
    for (int i = 0; i < 2; i++)
#pragma unroll
        for (int j = 0; j < 8; j++)
#pragma unroll
            for (int r = 0; r < 4; r++) c[i][j][r] = 0.f;

    const int NK = K / HBK;
    const __half* Ab = A + (size_t)brow * K;

    uint32_t smh_u32 = (uint32_t)__cvta_generic_to_shared(smh);
    int lr = (lane & 7) + ((lane >> 3) & 1) * 8;
    int lk = (lane >> 4) * 8;
    uint32_t a_off = (uint32_t)((wm * 32 + lr) * HSTRIDE + lk) * 2;
    uint32_t b_off = (uint32_t)(HA_STAGE + (lane & 15) * BPAD + wn * 64 +
                                (lane >> 4) * 8) * 2;

#pragma unroll
    for (int s = 0; s < NSTAGE - 1; s++) {
        __half* st = smh + s * HSTAGE;
        load_a_tile(st, Ab, K, s * HBK, tid);
        load_b_tile(st + HA_STAGE, B, N, bcol, s * HBK, tid);
        cp_commit();
    }

    for (int kt = 0; kt < NK; kt++) {
        cp_wait1();
        __syncthreads();

        if (kt + NSTAGE - 1 < NK) {
            __half* st = smh + ((kt + NSTAGE - 1) % NSTAGE) * HSTAGE;
            load_a_tile(st, Ab, K, (kt + NSTAGE - 1) * HBK, tid);
            load_b_tile(st + HA_STAGE, B, N, bcol, (kt + NSTAGE - 1) * HBK, tid);
        }
        cp_commit();

        uint32_t stage_base = smh_u32 + (uint32_t)((kt % NSTAGE) * HSTAGE * 2);

#pragma unroll
        for (int j = 0; j < 4; j++) {
            uint32_t a[2][4], b[8][2];
            uint32_t ja = stage_base + a_off + (uint32_t)(j * 32);
#pragma unroll
            for (int mt = 0; mt < 2; mt++)
                ldmatrix_x4(a[mt][0], a[mt][1], a[mt][2], a[mt][3],
                            ja + (uint32_t)(mt * 16 * HSTRIDE * 2));
            uint32_t jb = stage_base + b_off + (uint32_t)(j * 16 * BPAD * 2);
#pragma unroll
            for (int p = 0; p < 4; p++) {
                uint32_t r0, r1, r2, r3;
                ldmatrix_x4_trans(r0, r1, r2, r3, jb + (uint32_t)(p * 32));
                b[2 * p][0] = r0; b[2 * p][1] = r1;
                b[2 * p + 1][0] = r2; b[2 * p + 1][1] = r3;
            }
#pragma unroll
            for (int mt = 0; mt < 2; mt++)
#pragma unroll
                for (int nt = 0; nt < 8; nt++)
                    mma_f16(c[mt][nt], a[mt], b[nt]);
        }
    }

    int rope_here = do_rope && (bcol < 2 * DIM);
#pragma unroll
    for (int mt = 0; mt < 2; mt++) {
        int r0 = brow + wm * 32 + mt * 16 + g;
        int pos0 = r0 & (SEQ - 1);
        int pos1 = (r0 + 8) & (SEQ - 1);
#pragma unroll
        for (int nt = 0; nt < 8; nt++) {
            int col = bcol + wn * 64 + nt * 8 + 2 * t;
            float b0 = bias[col], b1 = bias[col + 1];
            float v00 = c[mt][nt][0] + b0, v01 = c[mt][nt][1] + b1;
            float v10 = c[mt][nt][2] + b0, v11 = c[mt][nt][3] + b1;
            if (rope_here) {
                int i = (col & (HD - 1)) >> 1;
                float c0 = g_cos[pos0 * (HD / 2) + i];
                float s0 = g_sin[pos0 * (HD / 2) + i];
                float c1 = g_cos[pos1 * (HD / 2) + i];
                float s1 = g_sin[pos1 * (HD / 2) + i];
                float n00 = v00 * c0 - v01 * s0;
                float n01 = v01 * c0 + v00 * s0;
                float n10 = v10 * c1 - v11 * s1;
                float n11 = v11 * c1 + v10 * s1;
                v00 = n00; v01 = n01; v10 = n10; v11 = n11;
            }
            if (Ch) {
                *(__half2*)(Ch + (size_t)r0 * N + col) = __floats2half2_rn(v00, v01);
                *(__half2*)(Ch + (size_t)(r0 + 8) * N + col) = __floats2half2_rn(v10, v11);
            } else {
                *(float2*)(C + (size_t)r0 * N + col) = make_float2(v00, v01);
                *(float2*)(C + (size_t)(r0 + 8) * N + col) = make_float2(v10, v11);
            }
        }
    }
}

// ---------------------------------------------------------------------------
// FP16 flash attention — occ 3, FQT=64, Q in registers, 2-stage KV ring,
// register P.  This round: scale folded into exp FFMA (raw-score max),
// warp-vote rescale skip, hoisted per-buffer ldmatrix bases.
// ---------------------------------------------------------------------------
#define FQT 64
#define FKT 64
#define KPADh 136
#define V_OFF (FKT * KPADh)
#define SKV (2 * FKT * KPADh)
#define FA_NSTG 2
#define FA_SMEM_BYTES (FA_NSTG * SKV * 2)   // 69632

__device__ __forceinline__ void fa_load_kv_async(__half* dst, const __half* ksrc,
                                                 int tid) {
#pragma unroll
    for (int v = 0; v < 8; v++) {
        int idx = v * 128 + tid;
        int row = idx >> 4, ch = idx & 15;
        cp_async16(dst + row * KPADh + ch * 8, ksrc + (size_t)row * QKVC + ch * 8);
    }
    const __half* vsrc = ksrc + DIM;
#pragma unroll
    for (int v = 0; v < 8; v++) {
        int idx = v * 128 + tid;
        int row = idx >> 4, ch = idx & 15;
        cp_async16(dst + V_OFF + row * KPADh + ch * 8,
                   vsrc + (size_t)row * QKVC + ch * 8);
    }
}

__global__ __launch_bounds__(128, 3)
void flash_attn_f16(const __half* __restrict__ qkv, __half* __restrict__ ctx) {
    int qtile = (int)gridDim.x - 1 - (int)blockIdx.x;   // heavy tiles first
    int head = blockIdx.y, batch = blockIdx.z;
    int q0 = qtile * FQT;
    int tid = threadIdx.x, warp = tid >> 5, lane = tid & 31;
    int g = lane >> 2, t = lane & 3;

    extern __shared__ __half smh[];
    __half* KV0 = smh;

    const float scale2 = 0.08838834764831845f * 1.4426950408889634f;
    const __half* qbase = qkv + (size_t)(batch * SEQ + q0) * QKVC + head * HD;
    const __half* kvbase = qkv + (size_t)(batch * SEQ) * QKVC + DIM + head * HD;

    int ntiles = qtile + 1;

    // Prologue: KV[0]
    fa_load_kv_async(KV0, kvbase, tid);
    cp_commit();

    // Q -> registers, directly in A-fragment layout
    uint32_t qa[8][4];
    {
        const __half* q0p = qbase + (size_t)(warp * 16 + g) * QKVC + 2 * t;
        const __half* q1p = q0p + (size_t)8 * QKVC;
#pragma unroll
        for (int j = 0; j < 8; j++) {
            qa[j][0] = *(const uint32_t*)(q0p + 16 * j);
            qa[j][1] = *(const uint32_t*)(q1p + 16 * j);
            qa[j][2] = *(const uint32_t*)(q0p + 16 * j + 8);
            qa[j][3] = *(const uint32_t*)(q1p + 16 * j + 8);
        }
    }

    uint32_t kv0_u32 = (uint32_t)__cvta_generic_to_shared(KV0);
    uint32_t lm_lane = (((lane & 15) * KPADh) + ((lane >> 4) * 8)) * 2;
    // Hoisted per-buffer ldmatrix bases
    uint32_t k_lm_buf[2], v_lm_buf[2];
    k_lm_buf[0] = kv0_u32 + lm_lane;
    k_lm_buf[1] = k_lm_buf[0] + SKV * 2;
    v_lm_buf[0] = k_lm_buf[0] + V_OFF * 2;
    v_lm_buf[1] = k_lm_buf[1] + V_OFF * 2;

    float o[8][2][4];
#pragma unroll
    for (int mt = 0; mt < 8; mt++)
#pragma unroll
        for (int nt = 0; nt < 2; nt++)
#pragma unroll
            for (int r = 0; r < 4; r++) o[mt][nt][r] = 0.f;

    // m kept in SCALED (exp2) domain; max reduced over RAW scores.
    float m_a = -INFINITY, m_b = -INFINITY, l_a = 0.f, l_b = 0.f;
    int rowa = q0 + warp * 16 + g;
    int rowb = rowa + 8;

    int buf = 0;
    for (int kt = 0; kt < ntiles; kt++) {
        cp_wait0();
        __syncthreads();

        if (kt + 1 < ntiles) {
            fa_load_kv_async(KV0 + (buf ^ 1) * SKV,
                             kvbase + (size_t)(kt + 1) * FKT * QKVC, tid);
            cp_commit();
        }
        uint32_t k_lm = k_lm_buf[buf];
        uint32_t v_lm = v_lm_buf[buf];

        // ---- S = Q @ K^T ----
        float sc[8][4];
#pragma unroll
        for (int nt = 0; nt < 8; nt++)
#pragma unroll
            for (int r = 0; r < 4; r++) sc[nt][r] = 0.f;

#pragma unroll
        for (int j = 0; j < 8; j++) {
            uint32_t b[8][2];
#pragma unroll
            for (int p = 0; p < 4; p++) {
                uint32_t r0, r1, r2, r3;
                ldmatrix_x4(r0, r1, r2, r3,
                            k_lm + (uint32_t)(p * 16 * KPADh) * 2 +
                            (uint32_t)(j * 32));
                b[2 * p][0] = r0; b[2 * p + 1][0] = r1;
                b[2 * p][1] = r2; b[2 * p + 1][1] = r3;
            }
#pragma unroll
            for (int nt = 0; nt < 8; nt++)
                mma_f16(sc[nt], qa[j], b[nt]);
        }

        // ---- causal mask on raw scores (diagonal tile only) ----
        if (kt == qtile) {
            int k0g = kt * FKT;
#pragma unroll
            for (int nt = 0; nt < 8; nt++) {
                int col = k0g + nt * 8 + 2 * t;
                if (col > rowa) sc[nt][0] = -INFINITY;
                if (col + 1 > rowa) sc[nt][1] = -INFINITY;
                if (col > rowb) sc[nt][2] = -INFINITY;
                if (col + 1 > rowb) sc[nt][3] = -INFINITY;
            }
        }

        // ---- max over raw scores (tree), scale once after reduction ----
        float ma0 = -INFINITY, ma1 = -INFINITY, mb0 = -INFINITY, mb1 = -INFINITY;
#pragma unroll
        for (int nt = 0; nt < 8; nt += 2) {
            ma0 = fmaxf(ma0, fmaxf(sc[nt][0], sc[nt][1]));
            ma1 = fmaxf(ma1, fmaxf(sc[nt + 1][0], sc[nt + 1][1]));
            mb0 = fmaxf(mb0, fmaxf(sc[nt][2], sc[nt][3]));
            mb1 = fmaxf(mb1, fmaxf(sc[nt + 1][2], sc[nt + 1][3]));
        }
        float tma = fmaxf(ma0, ma1), tmb = fmaxf(mb0, mb1);
        tma = fmaxf(tma, __shfl_xor_sync(0xffffffff, tma, 1));
        tma = fmaxf(tma, __shfl_xor_sync(0xffffffff, tma, 2));
        tmb = fmaxf(tmb, __shfl_xor_sync(0xffffffff, tmb, 1));
        tmb = fmaxf(tmb, __shfl_xor_sync(0xffffffff, tmb, 2));

        float nma = fmaxf(m_a, tma * scale2);
        float nmb = fmaxf(m_b, tmb * scale2);
        float ca = exp2f(m_a - nma), cb = exp2f(m_b - nmb);
        m_a = nma; m_b = nmb;

        // ---- p = exp2(sc*scale2 - m) via single FFMA + MUFU ----
        uint32_t pb[8][2];
        float sA0 = 0.f, sA1 = 0.f, sB0 = 0.f, sB1 = 0.f;
#pragma unroll
        for (int nt = 0; nt < 8; nt += 2) {
            float p0 = exp2f(fmaf(sc[nt][0], scale2, -nma));
            float p1 = exp2f(fmaf(sc[nt][1], scale2, -nma));
            float p2 = exp2f(fmaf(sc[nt][2], scale2, -nmb));
            float p3 = exp2f(fmaf(sc[nt][3], scale2, -nmb));
            pb[nt][0] = pack_half2(p0, p1);
            pb[nt][1] = pack_half2(p2, p3);
            sA0 += p0 + p1;
            sB0 += p2 + p3;
            float q0f = exp2f(fmaf(sc[nt + 1][0], scale2, -nma));
            float q1f = exp2f(fmaf(sc[nt + 1][1], scale2, -nma));
            float q2f = exp2f(fmaf(sc[nt + 1][2], scale2, -nmb));
            float q3f = exp2f(fmaf(sc[nt + 1][3], scale2, -nmb));
            pb[nt + 1][0] = pack_half2(q0f, q1f);
            pb[nt + 1][1] = pack_half2(q2f, q3f);
            sA1 += q0f + q1f;
            sB1 += q2f + q3f;
        }
        float sa = sA0 + sA1, sb = sB0 + sB1;
        sa += __shfl_xor_sync(0xffffffff, sa, 1);
        sa += __shfl_xor_sync(0xffffffff, sa, 2);
        sb += __shfl_xor_sync(0xffffffff, sb, 1);
        sb += __shfl_xor_sync(0xffffffff, sb, 2);
        l_a = l_a * ca + sa;
        l_b = l_b * cb + sb;

        // ---- rescale O^T only when some row max moved (warp vote) ----
        if (__any_sync(0xffffffff, (ca < 1.f) | (cb < 1.f))) {
            float c0a = __shfl_sync(0xffffffff, ca, 8 * t);
            float c1a = __shfl_sync(0xffffffff, ca, 8 * t + 4);
            float c0b = __shfl_sync(0xffffffff, cb, 8 * t);
            float c1b = __shfl_sync(0xffffffff, cb, 8 * t + 4);
#pragma unroll
            for (int mt = 0; mt < 8; mt++) {
                o[mt][0][0] *= c0a; o[mt][0][1] *= c1a;
                o[mt][0][2] *= c0a; o[mt][0][3] *= c1a;
                o[mt][1][0] *= c0b; o[mt][1][1] *= c1b;
                o[mt][1][2] *= c0b; o[mt][1][3] *= c1b;
            }
        }

        // ---- O^T += V^T @ P^T ----
#pragma unroll
        for (int j = 0; j < 4; j++) {
            uint32_t b0[2] = {pb[2 * j][0], pb[2 * j + 1][0]};
            uint32_t b1[2] = {pb[2 * j][1], pb[2 * j + 1][1]};
#pragma unroll
            for (int mt = 0; mt < 8; mt++) {
                uint32_t r0, r1, r2, r3;
                ldmatrix_x4_trans(r0, r1, r2, r3,
                                  v_lm + (uint32_t)(16 * j * KPADh + mt * 16) * 2);
                uint32_t a[4] = {r0, r2, r1, r3};
                mma_f16(o[mt][0], a, b0);
                mma_f16(o[mt][1], a, b1);
            }
        }

        buf ^= 1;
    }

    // ---- epilogue: O = O^T / l (l via shfl), fp16 out ----
    float l0a = __shfl_sync(0xffffffff, l_a, 8 * t);
    float l1a = __shfl_sync(0xffffffff, l_a, 8 * t + 4);
    float l0b = __shfl_sync(0xffffffff, l_b, 8 * t);
    float l1b = __shfl_sync(0xffffffff, l_b, 8 * t + 4);

#pragma unroll
    for (int nt = 0; nt < 2; nt++) {
        float il0 = 1.0f / (nt ? l0b : l0a);
        float il1 = 1.0f / (nt ? l1b : l1a);
        int q_loc = warp * 16 + nt * 8 + 2 * t;
        size_t r0 = (size_t)(batch * SEQ + q0 + q_loc) * DIM + head * HD;
        size_t r1 = r0 + DIM;
#pragma unroll
        for (int mt = 0; mt < 8; mt++) {
            int d = mt * 16 + g;
            ctx[r0 + d] = __float2half_rn(o[mt][nt][0] * il0);
            ctx[r1 + d] = __float2half_rn(o[mt][nt][1] * il1);
            ctx[r0 + d + 8] = __float2half_rn(o[mt][nt][2] * il0);
            ctx[r1 + d + 8] = __float2half_rn(o[mt][nt][3] * il1);
        }
    }
}

// ---------------------------------------------------------------------------
// Launch
// ---------------------------------------------------------------------------
extern "C" void kernel_launch(void* const* d_in, const int* in_sizes, int n_in,
                              void* d_out, int out_size) {
    const float* x      = (const float*)d_in[0];
    const float* Wqkv_w = (const float*)d_in[2];
    const float* Wqkv_b = (const float*)d_in[3];
    const float* Wout_w = (const float*)d_in[4];
    const float* Wout_b = (const float*)d_in[5];
    float* out = (float*)d_out;

    void *qkv_p, *ctx_p, *xh_p, *w1_p, *w2_p;
    cudaGetSymbolAddress(&qkv_p, g_qkvh);
    cudaGetSymbolAddress(&ctx_p, g_ctxh);
    cudaGetSymbolAddress(&xh_p, g_xh);
    cudaGetSymbolAddress(&w1_p, g_w1h);
    cudaGetSymbolAddress(&w2_p, g_w2h);
    __half* qkv = (__half*)qkv_p;
    __half* ctx = (__half*)ctx_p;
    __half* xh  = (__half*)xh_p;
    __half* w1h = (__half*)w1_p;
    __half* w2h = (__half*)w2_p;

    cudaFuncSetAttribute(gemm_fp16, cudaFuncAttributeMaxDynamicSharedMemorySize,
                         GEMM_SMEM_BYTES);
    cudaFuncSetAttribute(flash_attn_f16,
                         cudaFuncAttributeMaxDynamicSharedMemorySize, FA_SMEM_BYTES);

    // 0) Prep: fused conversions + RoPE tables (one launch)
    prep_all<<<(PREP_TOTAL + 255) / 256, 256>>>(x, Wqkv_w, Wout_w);

    // 1) QKV projection (fp16 MMA) with fused RoPE, fp16 output
    gemm_fp16<<<dim3(QKVC / BN, NTOK / BM), 256, GEMM_SMEM_BYTES>>>(
        xh, w1h, Wqkv_b, nullptr, qkv, NTOK, QKVC, DIM, 1);

    // 2) Flash attention (fp16 MMA; fp16 ctx)
    flash_attn_f16<<<dim3(SEQ / FQT, NH, BB), 128, FA_SMEM_BYTES>>>(qkv, ctx);

    // 3) Output projection (fp16 MMA, fp32 output)
    gemm_fp16<<<dim3(DIM / BN, NTOK / BM), 256, GEMM_SMEM_BYTES>>>(
        ctx, w2h, Wout_b, out, nullptr, NTOK, DIM, DIM, 0);
}